// round 16
// baseline (speedup 1.0000x reference)
#include <cuda_runtime.h>
#include <cstddef>
#include <cstdint>

#define B_   2
#define N_   768
#define BN_  1536
#define D_   512
#define E_   64
#define LN_EPS 1e-5f
#define PADR 68            // epilogue smem row pitch (floats)
#define JT   8             // j-tiles per block in epilogue
#define NBLK 576           // single wave at 4/SM (proven co-resident in R15)

// ---------------- scratch ----------------
__device__ float g_WR[D_ * E_];     // fused W_edges@W_rows, [d][f]
__device__ float g_WC[D_ * E_];     // fused W_edges@W_cols, [d][f]
__device__ float g_Rc[BN_ * E_];    // centered R'
__device__ float g_Cc[BN_ * E_];    // centered C'
__device__ float g_varR[BN_];
__device__ float g_varC[BN_];
__device__ int   g_wflag = 0;       // fusion-done counter (target 64)
__device__ int   g_rowflag[96];     // per-16-row-group counters (target 4)
__device__ int   g_done = 0;

// acquire-spin on a row group being fully produced
__device__ __forceinline__ void waitrow(int g) {
    volatile int* f = (volatile int*)(g_rowflag + g);
    if (*f < 4) { while (*f < 4) __nanosleep(40); }
    __threadfence();
}

extern __shared__ float sm[];

__global__ void __launch_bounds__(256, 4) kAll(
        const float* __restrict__ x,
        const float* __restrict__ Wr,
        const float* __restrict__ Wc,
        const float* __restrict__ We,
        const float* __restrict__ gamma,
        const float* __restrict__ beta,
        float* __restrict__ out) {
    int tid = threadIdx.x;
    int bid = blockIdx.x;

    // ============ Producer role A: weight fusion (blocks 0..63) =============
    if (bid < 64) {
        int gid = bid * 256 + tid;
        int d  = gid & 511;              // coalesced across warp
        int fh = gid >> 9;               // warp-uniform (broadcast We reads)
        const float* we0 = We + fh * E_;
        const float* we1 = We + (fh + 32) * E_;
        float ar0 = 0.f, ar1 = 0.f, ac0 = 0.f, ac1 = 0.f;
#pragma unroll 8
        for (int e = 0; e < E_; e++) {
            float wr = Wr[(size_t)e * D_ + d];
            float wc = Wc[(size_t)e * D_ + d];
            float w0 = we0[e], w1 = we1[e];
            ar0 = fmaf(w0, wr, ar0); ar1 = fmaf(w1, wr, ar1);
            ac0 = fmaf(w0, wc, ac0); ac1 = fmaf(w1, wc, ac1);
        }
        g_WR[d * E_ + fh]      = ar0;
        g_WR[d * E_ + fh + 32] = ar1;
        g_WC[d * E_ + fh]      = ac0;
        g_WC[d * E_ + fh + 32] = ac1;
        __threadfence();
        __syncthreads();
        if (tid == 0) atomicAdd(&g_wflag, 1);
    }
    // ============ Producer role B: row GEMM + stats (blocks 64..447) =========
    else if (bid < 448) {
        int pb   = bid - 64;             // 0..383
        int row0 = pb * 4;
        int rg = tid >> 6;               // row within tile (0..3)
        int kq = (tid >> 4) & 3;         // K-quarter (0..3)
        int f4 = tid & 15;               // float4 index within f (0..15)

        // wait for fused weights
        {
            volatile int* wf = (volatile int*)&g_wflag;
            if (*wf < 64) { while (*wf < 64) __nanosleep(40); }
            __threadfence();
        }

        float* xs = sm;                  // 4 x 512 = 2048 floats
        for (int idx = tid; idx < 512; idx += 256)
            ((float4*)xs)[idx] = ((const float4*)(x + (size_t)row0 * D_))[idx];
        __syncthreads();

        const float4* WR4 = (const float4*)g_WR;   // [dd][16 float4]
        const float4* WC4 = (const float4*)g_WC;
        const float*  xrow = xs + rg * 512 + kq * 128;
        float4 aR = make_float4(0.f, 0.f, 0.f, 0.f);
        float4 aC = make_float4(0.f, 0.f, 0.f, 0.f);
        int dbase = kq * 128;
#pragma unroll 8
        for (int dd = 0; dd < 128; dd++) {
            float xv = xrow[dd];
            float4 wr = WR4[(size_t)(dbase + dd) * 16 + f4];
            float4 wc = WC4[(size_t)(dbase + dd) * 16 + f4];
            aR.x = fmaf(xv, wr.x, aR.x); aR.y = fmaf(xv, wr.y, aR.y);
            aR.z = fmaf(xv, wr.z, aR.z); aR.w = fmaf(xv, wr.w, aR.w);
            aC.x = fmaf(xv, wc.x, aC.x); aC.y = fmaf(xv, wc.y, aC.y);
            aC.z = fmaf(xv, wc.z, aC.z); aC.w = fmaf(xv, wc.w, aC.w);
        }

        // kq-reduce via smem (P region after xs)
        float4* P4 = (float4*)(sm + 2048);          // 512 float4
        __syncthreads();                            // xs reads done
        P4[(rg * 4 + kq) * 16 + f4]       = aR;
        P4[256 + (rg * 4 + kq) * 16 + f4] = aC;
        __syncthreads();

        if (kq == 0) {                              // lanes 0..15 of warp rg*2
            float4 R = make_float4(0.f, 0.f, 0.f, 0.f);
            float4 C = make_float4(0.f, 0.f, 0.f, 0.f);
#pragma unroll
            for (int q = 0; q < 4; q++) {
                float4 pr = P4[(rg * 4 + q) * 16 + f4];
                float4 pc = P4[256 + (rg * 4 + q) * 16 + f4];
                R.x += pr.x; R.y += pr.y; R.z += pr.z; R.w += pr.w;
                C.x += pc.x; C.y += pc.y; C.z += pc.z; C.w += pc.w;
            }
            float sR = R.x + R.y + R.z + R.w;
            float qR = R.x * R.x + R.y * R.y + R.z * R.z + R.w * R.w;
            float sC = C.x + C.y + C.z + C.w;
            float qC = C.x * C.x + C.y * C.y + C.z * C.z + C.w * C.w;
#pragma unroll
            for (int o = 1; o < 16; o <<= 1) {
                sR += __shfl_xor_sync(0x0000FFFFu, sR, o, 16);
                qR += __shfl_xor_sync(0x0000FFFFu, qR, o, 16);
                sC += __shfl_xor_sync(0x0000FFFFu, sC, o, 16);
                qC += __shfl_xor_sync(0x0000FFFFu, qC, o, 16);
            }
            float mR = sR * (1.f / 64.f);
            float mC = sC * (1.f / 64.f);
            int row = row0 + rg;
            float4 oR = make_float4(R.x - mR, R.y - mR, R.z - mR, R.w - mR);
            float4 oC = make_float4(C.x - mC, C.y - mC, C.z - mC, C.w - mC);
            ((float4*)(g_Rc + (size_t)row * E_))[f4] = oR;
            ((float4*)(g_Cc + (size_t)row * E_))[f4] = oC;
            if (f4 == 0) {
                g_varR[row] = qR * (1.f / 64.f) - mR * mR;
                g_varC[row] = qC * (1.f / 64.f) - mC * mC;
            }
        }
        __threadfence();
        __syncthreads();                            // all writes fenced before flag
        if (tid == 0) atomicAdd(&g_rowflag[pb >> 2], 1);
    }

    // ================= Epilogue: ALL 576 blocks (R15 body + waits) ==========
    {
        float* rs  = sm;                 // 1088
        float* cs0 = sm + 1088;          // 1088
        float* cs1 = sm + 2176;          // 1088
        float* vR  = sm + 3264;          // 16
        float* vC0 = sm + 3280;          // 16
        float* vC1 = sm + 3296;          // 16
        float* inv = sm + 3312;          // 256

        int i0 = (bid % 48) * 16;
        int b  = (bid / 48) & 1;
        int jg = bid / 96;               // 0..5
        int rowR = b * N_ + i0;
        int rw = tid >> 4;
        int f4 = tid & 15;
        int gbase = b * 48 + jg * JT;    // first j-tile group

        __syncthreads();                 // producer smem use complete
        waitrow(b * 48 + (bid % 48));    // i-tile rows ready
        ((float4*)(rs + rw * PADR))[f4] =
            ((const float4*)(g_Rc + (size_t)(rowR + rw) * E_))[f4];
        if (tid < 16) vR[tid] = g_varR[rowR + tid];
        waitrow(gbase);                  // j-tile 0 rows ready
        {
            int rowC = b * N_ + jg * JT * 16;
            ((float4*)(cs0 + rw * PADR))[f4] =
                ((const float4*)(g_Cc + (size_t)(rowC + rw) * E_))[f4];
            if (tid < 16) vC0[tid] = g_varC[rowC + tid];
        }
        __syncthreads();

        float4 gm = __ldg((const float4*)gamma + f4);
        float4 bt = __ldg((const float4*)beta + f4);
        float4 rr = ((const float4*)(rs + rw * PADR))[f4];
        float4 u;
        u.x = rr.x * gm.x; u.y = rr.y * gm.y; u.z = rr.z * gm.z; u.w = rr.w * gm.w;

        for (int t = 0; t < JT; t++) {
            float* csc = (t & 1) ? cs1 : cs0;
            float* csn = (t & 1) ? cs0 : cs1;
            float* vCc = (t & 1) ? vC1 : vC0;
            float* vCn = (t & 1) ? vC0 : vC1;

            float4 pc;
            float pv = 0.f;
            if (t + 1 < JT) {
                waitrow(gbase + t + 1);  // next j-tile rows ready
                int rowCn = b * N_ + (jg * JT + t + 1) * 16;
                pc = ((const float4*)(g_Cc + (size_t)(rowCn + rw) * E_))[f4];
                if (tid < 16) pv = g_varC[rowCn + tid];
            }

            {
                int ii = tid >> 4, jj = tid & 15;
                const float4* r4 = (const float4*)(rs + ii * PADR);
                const float4* c4 = (const float4*)(csc + jj * PADR);
                float d = 0.f;
#pragma unroll
                for (int k = 0; k < 16; k++) {
                    float4 a = r4[k], c = c4[k];
                    d = fmaf(a.x, c.x, d);
                    d = fmaf(a.y, c.y, d);
                    d = fmaf(a.z, c.z, d);
                    d = fmaf(a.w, c.w, d);
                }
                float var = vR[ii] + vCc[jj] + d * (2.f / 64.f);
                inv[tid] = rsqrtf(var + LN_EPS);
            }
            __syncthreads();

            const float4* ivp = (const float4*)(inv + rw * 16);
            float4 iva = ivp[0], ivb = ivp[1], ivc = ivp[2], ivd = ivp[3];
            float ivs[16] = {iva.x, iva.y, iva.z, iva.w, ivb.x, ivb.y, ivb.z, ivb.w,
                             ivc.x, ivc.y, ivc.z, ivc.w, ivd.x, ivd.y, ivd.z, ivd.w};
            float4* op = (float4*)out +
                         ((size_t)(b * N_ + i0 + rw) * N_ + (jg * JT + t) * 16) * 16 + f4;
#pragma unroll
            for (int jj = 0; jj < 16; jj++) {
                float4 c = ((const float4*)(csc + jj * PADR))[f4];
                float iv = ivs[jj];
                float4 o;
                o.x = fmaf(fmaf(c.x, gm.x, u.x), iv, bt.x);
                o.y = fmaf(fmaf(c.y, gm.y, u.y), iv, bt.y);
                o.z = fmaf(fmaf(c.z, gm.z, u.z), iv, bt.z);
                o.w = fmaf(fmaf(c.w, gm.w, u.w), iv, bt.w);
                __stcs(op + (size_t)jj * 16, o);
            }

            if (t + 1 < JT) {
                ((float4*)(csn + rw * PADR))[f4] = pc;
                if (tid < 16) vCn[tid] = pv;
            }
            __syncthreads();
        }
    }

    // ---- reset flags for the next graph replay (last block to finish) ----
    if (tid == 0) {
        int d = atomicAdd(&g_done, 1);
        if (d == NBLK - 1) {
            g_wflag = 0;
#pragma unroll 4
            for (int i = 0; i < 96; i++) g_rowflag[i] = 0;
            g_done = 0;
            __threadfence();
        }
    }
}

// ---------------- launch -------------------------------------------------------
#define KALL_SMEM (4096 * 4)

extern "C" void kernel_launch(void* const* d_in, const int* in_sizes, int n_in,
                              void* d_out, int out_size) {
    const float* x     = (const float*)d_in[0];  // [2,768,512]
    const float* Wr    = (const float*)d_in[1];  // [64,512]
    const float* Wc    = (const float*)d_in[2];  // [64,512]
    const float* We    = (const float*)d_in[3];  // [64,64]
    const float* gamma = (const float*)d_in[4];  // [64]
    const float* beta  = (const float*)d_in[5];  // [64]
    float* out = (float*)d_out;                  // [2,768,768,64] fp32

    kAll<<<NBLK, 256, KALL_SMEM>>>(x, Wr, Wc, We, gamma, beta, out);
}

// round 17
// speedup vs baseline: 1.1911x; 1.1911x over previous
#include <cuda_runtime.h>
#include <cstddef>
#include <cstdint>

#define B_   2
#define N_   768
#define BN_  1536
#define D_   512
#define E_   64
#define LN_EPS 1e-5f
#define PADR 68            // kC smem row pitch (floats)
#define XP   130           // kB x-tile pitch (floats)
#define JT   8             // kC j-tiles per block

typedef unsigned long long ull;

// ---------------- scratch ----------------
__device__ float g_WR[D_ * E_];     // fused W_edges@W_rows, [d][f]
__device__ float g_WC[D_ * E_];     // fused W_edges@W_cols, [d][f]
__device__ float g_Rc[BN_ * E_];    // centered R'
__device__ float g_Cc[BN_ * E_];    // centered C'
__device__ float g_varR[BN_];
__device__ float g_varC[BN_];

// -------- f32x2 helpers --------
__device__ __forceinline__ void ffma2(ull& d, ull a, ull b) {
    asm("fma.rn.f32x2 %0, %1, %2, %0;" : "+l"(d) : "l"(a), "l"(b));
}
__device__ __forceinline__ ull pack2(float x) {
    ull r; unsigned u = __float_as_uint(x);
    asm("mov.b64 %0, {%1, %1};" : "=l"(r) : "r"(u));
    return r;
}

// ---------------- kernel A: K-split fused-weight build (measured 8.0us) -----
__global__ void __launch_bounds__(256) kA(const float* __restrict__ We,
                                          const float* __restrict__ Wr,
                                          const float* __restrict__ Wc) {
    int task = blockIdx.x * 256 + threadIdx.x;
    int k8 = task & 7;
    int d2 = (task >> 3) & 255;
    int fh = task >> 11;           // 0..31
    int f0 = fh, f1 = fh + 32;

    float2 ar0 = {0.f, 0.f}, ar1 = {0.f, 0.f};
    float2 ac0 = {0.f, 0.f}, ac1 = {0.f, 0.f};
    const float* we0p = We + f0 * E_ + k8 * 8;
    const float* we1p = We + f1 * E_ + k8 * 8;
#pragma unroll
    for (int e = 0; e < 8; e++) {
        int ge = k8 * 8 + e;
        float2 wr = *(const float2*)(Wr + (size_t)ge * D_ + d2 * 2);
        float2 wc = *(const float2*)(Wc + (size_t)ge * D_ + d2 * 2);
        float w0 = we0p[e], w1 = we1p[e];
        ar0.x = fmaf(w0, wr.x, ar0.x); ar0.y = fmaf(w0, wr.y, ar0.y);
        ar1.x = fmaf(w1, wr.x, ar1.x); ar1.y = fmaf(w1, wr.y, ar1.y);
        ac0.x = fmaf(w0, wc.x, ac0.x); ac0.y = fmaf(w0, wc.y, ac0.y);
        ac1.x = fmaf(w1, wc.x, ac1.x); ac1.y = fmaf(w1, wc.y, ac1.y);
    }
#pragma unroll
    for (int o = 4; o; o >>= 1) {
        ar0.x += __shfl_xor_sync(0xffffffffu, ar0.x, o);
        ar0.y += __shfl_xor_sync(0xffffffffu, ar0.y, o);
        ar1.x += __shfl_xor_sync(0xffffffffu, ar1.x, o);
        ar1.y += __shfl_xor_sync(0xffffffffu, ar1.y, o);
        ac0.x += __shfl_xor_sync(0xffffffffu, ac0.x, o);
        ac0.y += __shfl_xor_sync(0xffffffffu, ac0.y, o);
        ac1.x += __shfl_xor_sync(0xffffffffu, ac1.x, o);
        ac1.y += __shfl_xor_sync(0xffffffffu, ac1.y, o);
    }
    if (k8 == 0) {
        int d0 = d2 * 2;
        g_WR[(d0 + 0) * E_ + f0] = ar0.x;
        g_WR[(d0 + 1) * E_ + f0] = ar0.y;
        g_WR[(d0 + 0) * E_ + f1] = ar1.x;
        g_WR[(d0 + 1) * E_ + f1] = ar1.y;
        g_WC[(d0 + 0) * E_ + f0] = ac0.x;
        g_WC[(d0 + 1) * E_ + f0] = ac0.y;
        g_WC[(d0 + 0) * E_ + f1] = ac1.x;
        g_WC[(d0 + 1) * E_ + f1] = ac1.y;
    }
}

// ---------------- kernel B: row GEMM + stats, 192 blocks x 8 rows ------------
// 2 blocks/SM. smem: xs[1040] | wrs[8192] | wcs[8192]; P (8192) aliases wrs.
extern __shared__ float sm_b[];
__global__ void __launch_bounds__(256) kB(const float* __restrict__ x) {
    float* xs  = sm_b;            // 1040 floats (8 rows x pitch 130)
    float* wrs = sm_b + 1040;     // 8192
    float* wcs = wrs + 8192;      // 8192
    float* P   = sm_b + 1040;     // alias: 8192 floats

    int tid  = threadIdx.x;
    int f2   = tid & 31;
    int w    = tid >> 5;
    int row0 = blockIdx.x * 8;

    ull aR[8], aC[8];
#pragma unroll
    for (int r = 0; r < 8; r++) { aR[r] = 0ULL; aC[r] = 0ULL; }

    for (int c = 0; c < 4; c++) {
        int d0 = c * 128;
        // fused-weight chunk: contiguous float4 (L2-hot from kA)
        for (int idx = tid; idx < 2048; idx += 256) {
            ((float4*)wrs)[idx] = ((const float4*)(g_WR + d0 * E_))[idx];
            ((float4*)wcs)[idx] = ((const float4*)(g_WC + d0 * E_))[idx];
        }
        // x tile: 8 rows x 128 dd
        for (int idx = tid; idx < 512; idx += 256) {
            int r = idx >> 6, dd2 = idx & 63;
            *(float2*)(xs + r * XP + dd2 * 2) =
                *(const float2*)(x + (size_t)(row0 + r) * D_ + d0 + dd2 * 2);
        }
        __syncthreads();

        int wbase = w * 16;
#pragma unroll
        for (int p = 0; p < 8; p++) {
            int dd = wbase + p * 2;
            ull wr0 = *(const ull*)(wrs + dd * E_ + 2 * f2);
            ull wr1 = *(const ull*)(wrs + (dd + 1) * E_ + 2 * f2);
            ull wc0 = *(const ull*)(wcs + dd * E_ + 2 * f2);
            ull wc1 = *(const ull*)(wcs + (dd + 1) * E_ + 2 * f2);
#pragma unroll
            for (int r = 0; r < 8; r++) {
                float2 xv = *(const float2*)(xs + r * XP + dd);
                ull x0 = pack2(xv.x);
                ull x1 = pack2(xv.y);
                ffma2(aR[r], x0, wr0);
                ffma2(aR[r], x1, wr1);
                ffma2(aC[r], x0, wc0);
                ffma2(aC[r], x1, wc1);
            }
        }
        __syncthreads();
    }

    // per-warp partials: P[((w*2+arr)*8 + r)*64 + 2*f2]
#pragma unroll
    for (int r = 0; r < 8; r++) {
        *(ull*)(P + ((w * 2 + 0) * 8 + r) * E_ + 2 * f2) = aR[r];
        *(ull*)(P + ((w * 2 + 1) * 8 + r) * E_ + 2 * f2) = aC[r];
    }
    __syncthreads();

    // final reduce + stats: warp w owns row w; half-warps own R (arr=0) / C (arr=1)
    int row = tid >> 5;              // 0..7
    int arr = (tid >> 4) & 1;
    int fq  = tid & 15;
    float4 A = make_float4(0.f, 0.f, 0.f, 0.f);
#pragma unroll
    for (int ww = 0; ww < 8; ww++) {
        float4 p = *(const float4*)(P + ((ww * 2 + arr) * 8 + row) * E_ + fq * 4);
        A.x += p.x; A.y += p.y; A.z += p.z; A.w += p.w;
    }
    float s = A.x + A.y + A.z + A.w;
    float q = A.x * A.x + A.y * A.y + A.z * A.z + A.w * A.w;
#pragma unroll
    for (int o = 1; o < 16; o <<= 1) {
        s += __shfl_xor_sync(0xffffffffu, s, o, 16);
        q += __shfl_xor_sync(0xffffffffu, q, o, 16);
    }
    float m = s * (1.f / 64.f);
    int grow = row0 + row;
    float* dst  = arr ? g_Cc : g_Rc;
    float* vdst = arr ? g_varC : g_varR;
    float4 o4 = make_float4(A.x - m, A.y - m, A.z - m, A.w - m);
    *(float4*)(dst + (size_t)grow * E_ + fq * 4) = o4;
    if (fq == 0) vdst[grow] = q * (1.f / 64.f) - m * m;
}

// ---------------- kernel C: R8 pipelined epilogue (EXACT, measured 52.4us) ---
__global__ void __launch_bounds__(256, 4) kC(const float* __restrict__ gamma,
                                             const float* __restrict__ beta,
                                             float* __restrict__ out) {
    __shared__ float rs[16 * PADR];
    __shared__ float cs[2][16 * PADR];
    __shared__ float vR[16];
    __shared__ float vC[2][16];
    __shared__ float inv[256];

    int i0 = blockIdx.x * 16;
    int b  = blockIdx.y;
    int jg = blockIdx.z;
    int tid = threadIdx.x;
    int rowR = b * N_ + i0;
    int rw = tid >> 4;
    int f4 = tid & 15;

    ((float4*)(rs + rw * PADR))[f4] = ((const float4*)(g_Rc + (size_t)(rowR + rw) * E_))[f4];
    if (tid < 16) vR[tid] = g_varR[rowR + tid];
    {
        int rowC = b * N_ + jg * JT * 16;
        ((float4*)(cs[0] + rw * PADR))[f4] = ((const float4*)(g_Cc + (size_t)(rowC + rw) * E_))[f4];
        if (tid < 16) vC[0][tid] = g_varC[rowC + tid];
    }
    __syncthreads();

    float4 gm = __ldg((const float4*)gamma + f4);
    float4 bt = __ldg((const float4*)beta + f4);
    float4 rr = ((const float4*)(rs + rw * PADR))[f4];
    float4 u;
    u.x = rr.x * gm.x; u.y = rr.y * gm.y; u.z = rr.z * gm.z; u.w = rr.w * gm.w;

    for (int t = 0; t < JT; t++) {
        int cur = t & 1, nxt = cur ^ 1;
        float* csc = cs[cur];

        float4 pc;
        float pv = 0.f;
        if (t + 1 < JT) {
            int rowCn = b * N_ + (jg * JT + t + 1) * 16;
            pc = ((const float4*)(g_Cc + (size_t)(rowCn + rw) * E_))[f4];
            if (tid < 16) pv = g_varC[rowCn + tid];
        }

        {
            int ii = tid >> 4, jj = tid & 15;
            const float4* r4 = (const float4*)(rs + ii * PADR);
            const float4* c4 = (const float4*)(csc + jj * PADR);
            float d = 0.f;
#pragma unroll
            for (int k = 0; k < 16; k++) {
                float4 a = r4[k], c = c4[k];
                d = fmaf(a.x, c.x, d);
                d = fmaf(a.y, c.y, d);
                d = fmaf(a.z, c.z, d);
                d = fmaf(a.w, c.w, d);
            }
            float var = vR[ii] + vC[cur][jj] + d * (2.f / 64.f);
            inv[tid] = rsqrtf(var + LN_EPS);
        }
        __syncthreads();

        const float* invg = inv + rw * 16;
        const float4* ivp = (const float4*)invg;
        float4 iva = ivp[0], ivb = ivp[1], ivc = ivp[2], ivd = ivp[3];
        float ivs[16] = {iva.x, iva.y, iva.z, iva.w, ivb.x, ivb.y, ivb.z, ivb.w,
                         ivc.x, ivc.y, ivc.z, ivc.w, ivd.x, ivd.y, ivd.z, ivd.w};
        float4* op = (float4*)out +
                     ((size_t)(b * N_ + i0 + rw) * N_ + (jg * JT + t) * 16) * 16 + f4;
#pragma unroll
        for (int jj = 0; jj < 16; jj++) {
            float4 c = ((const float4*)(csc + jj * PADR))[f4];
            float iv = ivs[jj];
            float4 o;
            o.x = fmaf(fmaf(c.x, gm.x, u.x), iv, bt.x);
            o.y = fmaf(fmaf(c.y, gm.y, u.y), iv, bt.y);
            o.z = fmaf(fmaf(c.z, gm.z, u.z), iv, bt.z);
            o.w = fmaf(fmaf(c.w, gm.w, u.w), iv, bt.w);
            __stcs(op + (size_t)jj * 16, o);
        }

        if (t + 1 < JT) {
            ((float4*)(cs[nxt] + rw * PADR))[f4] = pc;
            if (tid < 16) vC[nxt][tid] = pv;
        }
        __syncthreads();
    }
}

// ---------------- launch -------------------------------------------------------
#define KB_SMEM ((1040 + 8192 + 8192) * 4)

extern "C" void kernel_launch(void* const* d_in, const int* in_sizes, int n_in,
                              void* d_out, int out_size) {
    const float* x     = (const float*)d_in[0];  // [2,768,512]
    const float* Wr    = (const float*)d_in[1];  // [64,512]
    const float* Wc    = (const float*)d_in[2];  // [64,512]
    const float* We    = (const float*)d_in[3];  // [64,64]
    const float* gamma = (const float*)d_in[4];  // [64]
    const float* beta  = (const float*)d_in[5];  // [64]
    float* out = (float*)d_out;                  // [2,768,768,64] fp32

    static int smem_set = 0;
    if (!smem_set) {
        cudaFuncSetAttribute(kB, cudaFuncAttributeMaxDynamicSharedMemorySize, KB_SMEM);
        smem_set = 1;
    }

    kA<<<256, 256>>>(We, Wr, Wc);
    kB<<<192, 256, KB_SMEM>>>(x);
    kC<<<dim3(N_ / 16, B_, N_ / 16 / JT), 256>>>(gamma, beta, out);
}